// round 13
// baseline (speedup 1.0000x reference)
#include <cuda_runtime.h>
#include <cstdint>
#include <math.h>

// Problem constants
#define DDIM   1024
#define NEXP   8
#define NTOK   8192
#define NPAIR  (NTOK * 2)

// GEMM tiling: CTA 128x128, 8 warps of 32x64, BK=32, 3-stage cp.async, 2 CTA/SM
#define BM 128
#define BN 128
#define BK 32
#define STAGES 3
#define A_BYTES (BM * BK * 4)              // 16384
#define B_BYTES (BN * BK * 4)              // 16384
#define STAGE_BYTES (A_BYTES + B_BYTES)    // 32768
#define SMEM_BYTES (STAGES * STAGE_BYTES)  // 98304

// -------- device scratch --------
__device__ float g_rdelta[(size_t)NTOK * DDIM];     // tf32-rounded, k8-pair-permuted delta
__device__ float g_rW[(size_t)NEXP * DDIM * DDIM];  // tf32-rounded, k8-pair-permuted expert_W
__device__ int   g_list[NEXP * NPAIR];
__device__ int   g_count[NEXP];
__device__ int   g_expert[NPAIR];
__device__ float g_weight[NPAIR];

// -------- helpers --------
__device__ __forceinline__ float to_tf32(float x) {
    uint32_t u;
    asm("cvt.rna.tf32.f32 %0, %1;" : "=r"(u) : "f"(x));
    return __uint_as_float(u);
}
__device__ __forceinline__ uint32_t smem_u32(const void* p) {
    uint32_t a;
    asm("{ .reg .u64 t; cvta.to.shared.u64 t, %1; cvt.u32.u64 %0, t; }" : "=r"(a) : "l"(p));
    return a;
}

__device__ __forceinline__ void cp_async16(uint32_t saddr, const void* gaddr) {
    asm volatile("cp.async.cg.shared.global [%0], [%1], 16;\n" :: "r"(saddr), "l"(gaddr));
}
__device__ __forceinline__ void cp_commit() { asm volatile("cp.async.commit_group;\n" ::: "memory"); }
template <int N>
__device__ __forceinline__ void cp_wait() { asm volatile("cp.async.wait_group %0;\n" :: "n"(N) : "memory"); }

__device__ __forceinline__ float2 lds64(uint32_t a) {
    float2 v;
    asm volatile("ld.shared.v2.f32 {%0,%1}, [%2];" : "=f"(v.x), "=f"(v.y) : "r"(a));
    return v;
}
__device__ __forceinline__ void red_add_f32(float* gptr, float v) {
    asm volatile("red.global.add.f32 [%0], %1;" :: "l"(gptr), "f"(v) : "memory");
}

__device__ __forceinline__ void mma_tf32(float* c,
                                         float a0, float a1, float a2, float a3,
                                         float b0, float b1) {
    asm volatile(
        "mma.sync.aligned.m16n8k8.row.col.f32.tf32.tf32.f32 "
        "{%0,%1,%2,%3}, {%4,%5,%6,%7}, {%8,%9}, {%0,%1,%2,%3};\n"
        : "+f"(c[0]), "+f"(c[1]), "+f"(c[2]), "+f"(c[3])
        : "r"(__float_as_uint(a0)), "r"(__float_as_uint(a1)),
          "r"(__float_as_uint(a2)), "r"(__float_as_uint(a3)),
          "r"(__float_as_uint(b0)), "r"(__float_as_uint(b1)));
}

// -------- kernel 0: tf32 pre-round + k8 fragment-pair permute --------
// Per 8 floats [k0..k7] -> [k0,k4,k1,k5,k2,k6,k3,k7] (pairs (kq, kq+4) adjacent).
#define ND8 (NTOK * DDIM / 8)
#define NW8 (NEXP * DDIM * DDIM / 8)
__global__ void round_kernel(const float* __restrict__ delta, float* __restrict__ rdelta,
                             const float* __restrict__ W, float* __restrict__ rW) {
    int i = blockIdx.x * blockDim.x + threadIdx.x;
    const float4* s;
    float4* d;
    if (i < ND8) { s = (const float4*)delta + 2 * (size_t)i; d = (float4*)rdelta + 2 * (size_t)i; }
    else         { size_t j = i - ND8; if (j >= NW8) return;
                   s = (const float4*)W + 2 * j; d = (float4*)rW + 2 * j; }
    float4 i0 = s[0], i1 = s[1];
    float4 o0, o1;
    o0.x = to_tf32(i0.x); o0.y = to_tf32(i1.x); o0.z = to_tf32(i0.y); o0.w = to_tf32(i1.y);
    o1.x = to_tf32(i0.z); o1.y = to_tf32(i1.z); o1.z = to_tf32(i0.w); o1.w = to_tf32(i1.w);
    d[0] = o0; d[1] = o1;
}

// -------- kernel 1: gating (one warp per token) --------
__global__ void gate_kernel(const float* __restrict__ x,
                            const float* __restrict__ gw,
                            const float* __restrict__ gb) {
    int warp = (blockIdx.x * blockDim.x + threadIdx.x) >> 5;
    int lane = threadIdx.x & 31;
    if (warp >= NTOK) return;
    const float* xr = x + (size_t)warp * DDIM;

    float acc[NEXP];
#pragma unroll
    for (int e = 0; e < NEXP; e++) acc[e] = 0.f;
    for (int i = lane; i < DDIM; i += 32) {
        float v = xr[i];
#pragma unroll
        for (int e = 0; e < NEXP; e++) acc[e] += v * gw[e * DDIM + i];
    }
#pragma unroll
    for (int e = 0; e < NEXP; e++) {
#pragma unroll
        for (int o = 16; o > 0; o >>= 1) acc[e] += __shfl_xor_sync(0xffffffffu, acc[e], o);
    }
    if (lane == 0) {
        float logits[NEXP];
#pragma unroll
        for (int e = 0; e < NEXP; e++) logits[e] = acc[e] + gb[e];
        int i0 = 0; float v0 = logits[0];
#pragma unroll
        for (int e = 1; e < NEXP; e++) if (logits[e] > v0) { v0 = logits[e]; i0 = e; }
        int i1 = -1; float v1 = -3.4e38f;
#pragma unroll
        for (int e = 0; e < NEXP; e++) if (e != i0 && logits[e] > v1) { v1 = logits[e]; i1 = e; }
        float e1 = expf(v1 - v0);
        float inv = 1.0f / (1.0f + e1);
        g_expert[warp * 2 + 0] = i0;
        g_expert[warp * 2 + 1] = i1;
        g_weight[warp * 2 + 0] = inv;
        g_weight[warp * 2 + 1] = e1 * inv;
    }
}

// -------- kernel 2: grouping, one block per expert --------
#define GT   1024
#define GPER (NPAIR / GT)   // 16
__global__ void __launch_bounds__(GT) group_kernel() {
    const int e = blockIdx.x;
    const int t = threadIdx.x;
    const int warp = t >> 5;
    const int lane = t & 31;
    __shared__ int s_tot[32];

    const int base = t * GPER;
    unsigned mask = 0;
    int cnt = 0;
#pragma unroll
    for (int i = 0; i < GPER; i++) {
        if (g_expert[base + i] == e) { mask |= (1u << i); cnt++; }
    }
    int incl = cnt;
#pragma unroll
    for (int o = 1; o < 32; o <<= 1) {
        int u = __shfl_up_sync(0xffffffffu, incl, o);
        if (lane >= o) incl += u;
    }
    if (lane == 31) s_tot[warp] = incl;
    __syncthreads();
    if (warp == 0) {
        int v = s_tot[lane];
        int orig = v;
#pragma unroll
        for (int o = 1; o < 32; o <<= 1) {
            int u = __shfl_up_sync(0xffffffffu, v, o);
            if (lane >= o) v += u;
        }
        if (lane == 31) g_count[e] = v;
        s_tot[lane] = v - orig;
    }
    __syncthreads();

    int off = s_tot[warp] + incl - cnt;
    int* lst = g_list + e * NPAIR;
    while (mask) {
        int i = __ffs(mask) - 1;
        mask &= mask - 1;
        lst[off++] = base + i;
    }
}

// -------- kernel 3: grouped GEMM, LDS.64 conflict-free fragments --------
// smem chunk placement: 16B chunk c_g of row r stored at c_s = c_g ^ ((r&3)<<1).
// Fragment read offset (per ks): 16*((2ks + (qid>>1)) ^ ((gid&3)<<1)) + 8*(qid&1).
// Bank-slot per half-warp = 2*c_s + (qid&1): bijective -> conflict-free.
__global__ void __launch_bounds__(256, 2) gemm_kernel(const float* __restrict__ eb,
                                                      float* __restrict__ out) {
    const int e   = blockIdx.z;
    const int cnt = g_count[e];
    const int m0  = blockIdx.y * BM;
    if (m0 >= cnt) return;
    const int n0  = blockIdx.x * BN;

    extern __shared__ __align__(1024) char smem[];
    __shared__ int   s_pid[BM];
    __shared__ int   s_tok[BM];
    __shared__ float s_w[BM];

    const uint32_t smem_base = smem_u32(smem);
    const int tid = threadIdx.x;
    const int wid = tid >> 5;
    const int lane = tid & 31;
    const int warpM = wid & 3;    // 4 x 32-row bands
    const int warpN = wid >> 2;   // 2 x 64-col bands
    const int gid = lane >> 2;    // 0..7
    const int qid = lane & 3;     // 0..3

    if (tid < BM) {
        int p = (m0 + tid < cnt) ? g_list[e * NPAIR + m0 + tid] : -1;
        s_pid[tid] = p;
        s_tok[tid] = (p >= 0) ? (p >> 1) : 0;
        s_w[tid]   = (p >= 0) ? g_weight[p] : 0.f;
    }
    __syncthreads();

    const float* __restrict__ Wb = g_rW + (size_t)e * DDIM * DDIM;
    const int NKB = DDIM / BK;  // 32

    auto issue_loads = [&](int kb) {
        const uint32_t sbase = smem_base + (uint32_t)(kb % STAGES) * STAGE_BYTES;
        const int kbase = kb * BK;
#pragma unroll
        for (int i = 0; i < 4; i++) {
            int idx = tid + i * 256;
            int r = idx >> 3, c4 = idx & 7;
            const float* g = g_rdelta + (size_t)s_tok[r] * DDIM + kbase + c4 * 4;
            cp_async16(sbase + (uint32_t)(r * 128 + 16 * (c4 ^ ((r & 3) << 1))), g);
        }
#pragma unroll
        for (int i = 0; i < 4; i++) {
            int idx = tid + i * 256;
            int r = idx >> 3, c4 = idx & 7;
            const float* g = Wb + (size_t)(n0 + r) * DDIM + kbase + c4 * 4;
            cp_async16(sbase + A_BYTES + (uint32_t)(r * 128 + 16 * (c4 ^ ((r & 3) << 1))), g);
        }
        cp_commit();
    };

    // per-ks fragment column offsets (constant per thread)
    uint32_t koffs[4];
#pragma unroll
    for (int ks = 0; ks < 4; ks++)
        koffs[ks] = (uint32_t)(16 * ((2 * ks + (qid >> 1)) ^ ((gid & 3) << 1)) + 8 * (qid & 1));

    // row bases: A rows (warpM*32 + {0,8,16,24} + gid), B rows (warpN*64 + nt*8 + gid)
    uint32_t abase[4], bbase[8];
#pragma unroll
    for (int i = 0; i < 4; i++)
        abase[i] = (uint32_t)((warpM * 32 + i * 8 + gid) * 128);
#pragma unroll
    for (int nt = 0; nt < 8; nt++)
        bbase[nt] = (uint32_t)(A_BYTES + (warpN * 64 + nt * 8 + gid) * 128);

    float acc[2][8][4];
#pragma unroll
    for (int mt = 0; mt < 2; mt++)
#pragma unroll
        for (int nt = 0; nt < 8; nt++)
#pragma unroll
            for (int j = 0; j < 4; j++) acc[mt][nt][j] = 0.f;

    issue_loads(0);
    issue_loads(1);

    for (int kb = 0; kb < NKB; kb++) {
        if (kb + 2 < NKB) cp_wait<1>(); else cp_wait<0>();
        __syncthreads();
        if (kb + 2 < NKB) issue_loads(kb + 2);

        const uint32_t sbase = smem_base + (uint32_t)(kb % STAGES) * STAGE_BYTES;

#pragma unroll
        for (int ks = 0; ks < 4; ks++) {
            const uint32_t koff = sbase + koffs[ks];
            // A: 4 x lds64 -> (a0,a2) / (a1,a3) per mt band
            const float2 a00 = lds64(koff + abase[0]);   // mt0 row r0: (a0, a2)
            const float2 a01 = lds64(koff + abase[1]);   // mt0 row r1: (a1, a3)
            const float2 a10 = lds64(koff + abase[2]);   // mt1 row r0
            const float2 a11 = lds64(koff + abase[3]);   // mt1 row r1
#pragma unroll
            for (int nt = 0; nt < 8; nt++) {
                const float2 vb = lds64(koff + bbase[nt]);
                mma_tf32(acc[0][nt], a00.x, a01.x, a00.y, a01.y, vb.x, vb.y);
                mma_tf32(acc[1][nt], a10.x, a11.x, a10.y, a11.y, vb.x, vb.y);
            }
        }
    }

    // fused epilogue: out[tok, c] += w * (acc + bias[e, c])
#pragma unroll
    for (int mt = 0; mt < 2; mt++) {
        int r0 = warpM * 32 + mt * 16 + gid;
        int r1 = r0 + 8;
        int p0 = s_pid[r0];
        int p1 = s_pid[r1];
        float w0 = s_w[r0], w1 = s_w[r1];
        float* o0 = out + (size_t)s_tok[r0] * DDIM;
        float* o1 = out + (size_t)s_tok[r1] * DDIM;
#pragma unroll
        for (int nt = 0; nt < 8; nt++) {
            int c = n0 + warpN * 64 + nt * 8 + qid * 2;
            const float2 bv = *(const float2*)(eb + (size_t)e * DDIM + c);
            if (p0 >= 0) {
                red_add_f32(o0 + c + 0, w0 * (acc[mt][nt][0] + bv.x));
                red_add_f32(o0 + c + 1, w0 * (acc[mt][nt][1] + bv.y));
            }
            if (p1 >= 0) {
                red_add_f32(o1 + c + 0, w1 * (acc[mt][nt][2] + bv.x));
                red_add_f32(o1 + c + 1, w1 * (acc[mt][nt][3] + bv.y));
            }
        }
    }
}

// -------- launch --------
extern "C" void kernel_launch(void* const* d_in, const int* in_sizes, int n_in,
                              void* d_out, int out_size) {
    const float* input_feat = (const float*)d_in[0];
    const float* delta      = (const float*)d_in[1];
    const float* gate_W     = (const float*)d_in[2];
    const float* gate_b     = (const float*)d_in[3];
    const float* expert_W   = (const float*)d_in[4];
    const float* expert_b   = (const float*)d_in[5];
    float* out = (float*)d_out;

    cudaFuncSetAttribute(gemm_kernel, cudaFuncAttributeMaxDynamicSharedMemorySize, SMEM_BYTES);

    float* rdelta; cudaGetSymbolAddress((void**)&rdelta, g_rdelta);
    float* rW;     cudaGetSymbolAddress((void**)&rW, g_rW);

    cudaMemsetAsync(out, 0, (size_t)out_size * sizeof(float));
    round_kernel<<<(ND8 + NW8 + 255) / 256, 256>>>(delta, rdelta, expert_W, rW);
    gate_kernel<<<NTOK / 8, 256>>>(input_feat, gate_W, gate_b);
    group_kernel<<<NEXP, GT>>>();
    dim3 grid(DDIM / BN, NPAIR / BM, NEXP);
    gemm_kernel<<<grid, 256, SMEM_BYTES>>>(expert_b, out);
}

// round 14
// speedup vs baseline: 1.0827x; 1.0827x over previous
#include <cuda_runtime.h>
#include <cstdint>
#include <math.h>

// Problem constants
#define DDIM   1024
#define NEXP   8
#define NTOK   8192
#define NPAIR  (NTOK * 2)

// GEMM tiling: CTA 128x128 with 4 warps of 64x64, BK=32, 3-stage, 2 CTA/SM
#define BM 128
#define BN 128
#define BK 32
#define STAGES 3
#define CTA_THREADS 128
#define A_BYTES (BM * BK * 4)              // 16384
#define B_BYTES (BN * BK * 4)              // 16384
#define STAGE_BYTES (A_BYTES + B_BYTES)    // 32768
#define SMEM_BYTES (STAGES * STAGE_BYTES)  // 98304

// -------- device scratch --------
__device__ float g_rdelta[(size_t)NTOK * DDIM];     // tf32-rounded delta
__device__ float g_rW[(size_t)NEXP * DDIM * DDIM];  // tf32-rounded expert_W
__device__ int   g_list[NEXP * NPAIR];
__device__ int   g_count[NEXP];
__device__ int   g_expert[NPAIR];
__device__ float g_weight[NPAIR];

// -------- helpers --------
__device__ __forceinline__ float to_tf32(float x) {
    uint32_t u;
    asm("cvt.rna.tf32.f32 %0, %1;" : "=r"(u) : "f"(x));
    return __uint_as_float(u);
}
__device__ __forceinline__ uint32_t smem_u32(const void* p) {
    uint32_t a;
    asm("{ .reg .u64 t; cvta.to.shared.u64 t, %1; cvt.u32.u64 %0, t; }" : "=r"(a) : "l"(p));
    return a;
}
__device__ __forceinline__ uint32_t swz128(uint32_t off) { return off ^ ((off >> 3) & 0x70u); }

__device__ __forceinline__ void cp_async16(uint32_t saddr, const void* gaddr) {
    asm volatile("cp.async.cg.shared.global [%0], [%1], 16;\n" :: "r"(saddr), "l"(gaddr));
}
__device__ __forceinline__ void cp_commit() { asm volatile("cp.async.commit_group;\n" ::: "memory"); }
template <int N>
__device__ __forceinline__ void cp_wait() { asm volatile("cp.async.wait_group %0;\n" :: "n"(N) : "memory"); }

__device__ __forceinline__ float lds32(uint32_t a) {
    float v;
    asm volatile("ld.shared.f32 %0, [%1];" : "=f"(v) : "r"(a));
    return v;
}
__device__ __forceinline__ void red_add_f32(float* gptr, float v) {
    asm volatile("red.global.add.f32 [%0], %1;" :: "l"(gptr), "f"(v) : "memory");
}

__device__ __forceinline__ void mma_tf32(float* c, const float* a, const float* b) {
    asm volatile(
        "mma.sync.aligned.m16n8k8.row.col.f32.tf32.tf32.f32 "
        "{%0,%1,%2,%3}, {%4,%5,%6,%7}, {%8,%9}, {%0,%1,%2,%3};\n"
        : "+f"(c[0]), "+f"(c[1]), "+f"(c[2]), "+f"(c[3])
        : "r"(__float_as_uint(a[0])), "r"(__float_as_uint(a[1])),
          "r"(__float_as_uint(a[2])), "r"(__float_as_uint(a[3])),
          "r"(__float_as_uint(b[0])), "r"(__float_as_uint(b[1])));
}

// -------- kernel 0: tf32 pre-round, both tensors --------
#define ND4 (NTOK * DDIM / 4)
#define NW4 (NEXP * DDIM * DDIM / 4)
__global__ void round_kernel(const float* __restrict__ delta, float* __restrict__ rdelta,
                             const float* __restrict__ W, float* __restrict__ rW) {
    int i = blockIdx.x * blockDim.x + threadIdx.x;
    const float4* s;
    float4* d;
    if (i < ND4) { s = (const float4*)delta + i; d = (float4*)rdelta + i; }
    else         { int j = i - ND4; if (j >= NW4) return; s = (const float4*)W + j; d = (float4*)rW + j; }
    float4 v = *s;
    v.x = to_tf32(v.x); v.y = to_tf32(v.y); v.z = to_tf32(v.z); v.w = to_tf32(v.w);
    *d = v;
}

// -------- kernel 1: gating (one warp per token) --------
__global__ void gate_kernel(const float* __restrict__ x,
                            const float* __restrict__ gw,
                            const float* __restrict__ gb) {
    int warp = (blockIdx.x * blockDim.x + threadIdx.x) >> 5;
    int lane = threadIdx.x & 31;
    if (warp >= NTOK) return;
    const float* xr = x + (size_t)warp * DDIM;

    float acc[NEXP];
#pragma unroll
    for (int e = 0; e < NEXP; e++) acc[e] = 0.f;
    for (int i = lane; i < DDIM; i += 32) {
        float v = xr[i];
#pragma unroll
        for (int e = 0; e < NEXP; e++) acc[e] += v * gw[e * DDIM + i];
    }
#pragma unroll
    for (int e = 0; e < NEXP; e++) {
#pragma unroll
        for (int o = 16; o > 0; o >>= 1) acc[e] += __shfl_xor_sync(0xffffffffu, acc[e], o);
    }
    if (lane == 0) {
        float logits[NEXP];
#pragma unroll
        for (int e = 0; e < NEXP; e++) logits[e] = acc[e] + gb[e];
        int i0 = 0; float v0 = logits[0];
#pragma unroll
        for (int e = 1; e < NEXP; e++) if (logits[e] > v0) { v0 = logits[e]; i0 = e; }
        int i1 = -1; float v1 = -3.4e38f;
#pragma unroll
        for (int e = 0; e < NEXP; e++) if (e != i0 && logits[e] > v1) { v1 = logits[e]; i1 = e; }
        float e1 = expf(v1 - v0);
        float inv = 1.0f / (1.0f + e1);
        g_expert[warp * 2 + 0] = i0;
        g_expert[warp * 2 + 1] = i1;
        g_weight[warp * 2 + 0] = inv;
        g_weight[warp * 2 + 1] = e1 * inv;
    }
}

// -------- kernel 2: grouping, one block per expert --------
#define GT   1024
#define GPER (NPAIR / GT)   // 16
__global__ void __launch_bounds__(GT) group_kernel() {
    const int e = blockIdx.x;
    const int t = threadIdx.x;
    const int warp = t >> 5;
    const int lane = t & 31;
    __shared__ int s_tot[32];

    const int base = t * GPER;
    unsigned mask = 0;
    int cnt = 0;
#pragma unroll
    for (int i = 0; i < GPER; i++) {
        if (g_expert[base + i] == e) { mask |= (1u << i); cnt++; }
    }
    int incl = cnt;
#pragma unroll
    for (int o = 1; o < 32; o <<= 1) {
        int u = __shfl_up_sync(0xffffffffu, incl, o);
        if (lane >= o) incl += u;
    }
    if (lane == 31) s_tot[warp] = incl;
    __syncthreads();
    if (warp == 0) {
        int v = s_tot[lane];
        int orig = v;
#pragma unroll
        for (int o = 1; o < 32; o <<= 1) {
            int u = __shfl_up_sync(0xffffffffu, v, o);
            if (lane >= o) v += u;
        }
        if (lane == 31) g_count[e] = v;
        s_tot[lane] = v - orig;
    }
    __syncthreads();

    int off = s_tot[warp] + incl - cnt;
    int* lst = g_list + e * NPAIR;
    while (mask) {
        int i = __ffs(mask) - 1;
        mask &= mask - 1;
        lst[off++] = base + i;
    }
}

// -------- kernel 3: grouped GEMM, 4 warps of 64x64, 2 CTA/SM, fused epilogue --------
__global__ void __launch_bounds__(CTA_THREADS, 2) gemm_kernel(const float* __restrict__ eb,
                                                              float* __restrict__ out) {
    const int e   = blockIdx.z;
    const int cnt = g_count[e];
    const int m0  = blockIdx.y * BM;
    if (m0 >= cnt) return;
    const int n0  = blockIdx.x * BN;

    extern __shared__ __align__(1024) char smem[];
    __shared__ int   s_pid[BM];
    __shared__ int   s_tok[BM];
    __shared__ float s_w[BM];

    const uint32_t smem_base = smem_u32(smem);
    const int tid = threadIdx.x;
    const int wid = tid >> 5;
    const int lane = tid & 31;
    const int warpM = wid & 1;    // 2 x 64-row bands
    const int warpN = wid >> 1;   // 2 x 64-col bands
    const int gid = lane >> 2;    // 0..7
    const int qid = lane & 3;     // 0..3

    if (tid < BM) {
        int p = (m0 + tid < cnt) ? g_list[e * NPAIR + m0 + tid] : -1;
        s_pid[tid] = p;
        s_tok[tid] = (p >= 0) ? (p >> 1) : 0;
        s_w[tid]   = (p >= 0) ? g_weight[p] : 0.f;
    }
    __syncthreads();

    const float* __restrict__ Wb = g_rW + (size_t)e * DDIM * DDIM;
    const int NKB = DDIM / BK;  // 32

    auto issue_loads = [&](int kb) {
        const uint32_t sbase = smem_base + (uint32_t)(kb % STAGES) * STAGE_BYTES;
        const int kbase = kb * BK;
        // A: 1024 chunks of 16B, 8 per thread (128 threads)
#pragma unroll
        for (int i = 0; i < 8; i++) {
            int idx = tid + i * CTA_THREADS;
            int r = idx >> 3, c4 = idx & 7;
            const float* g = g_rdelta + (size_t)s_tok[r] * DDIM + kbase + c4 * 4;
            cp_async16(sbase + swz128((uint32_t)(r * 128 + c4 * 16)), g);
        }
        // B: 1024 chunks, 8 per thread
#pragma unroll
        for (int i = 0; i < 8; i++) {
            int idx = tid + i * CTA_THREADS;
            int r = idx >> 3, c4 = idx & 7;
            const float* g = Wb + (size_t)(n0 + r) * DDIM + kbase + c4 * 4;
            cp_async16(sbase + A_BYTES + swz128((uint32_t)(r * 128 + c4 * 16)), g);
        }
        cp_commit();
    };

    // R9-proven fragment addressing: Q = r*128 + qid*4 | ((r&7)<<4), r&7==gid
    uint32_t qa[8], qb[8];
#pragma unroll
    for (int mt = 0; mt < 4; mt++) {
        int r0 = warpM * 64 + mt * 16 + gid;
        int r1 = r0 + 8;
        qa[mt * 2 + 0] = (uint32_t)(r0 * 128 + qid * 4) | (uint32_t)((r0 & 7) << 4);
        qa[mt * 2 + 1] = (uint32_t)(r1 * 128 + qid * 4) | (uint32_t)((r1 & 7) << 4);
    }
#pragma unroll
    for (int nt = 0; nt < 8; nt++) {
        int n = warpN * 64 + nt * 8 + gid;
        qb[nt] = (uint32_t)(A_BYTES + n * 128 + qid * 4) | (uint32_t)((n & 7) << 4);
    }

    float acc[4][8][4];
#pragma unroll
    for (int mt = 0; mt < 4; mt++)
#pragma unroll
        for (int nt = 0; nt < 8; nt++)
#pragma unroll
            for (int j = 0; j < 4; j++) acc[mt][nt][j] = 0.f;

    issue_loads(0);
    issue_loads(1);

    for (int kb = 0; kb < NKB; kb++) {
        if (kb + 2 < NKB) cp_wait<1>(); else cp_wait<0>();
        __syncthreads();
        if (kb + 2 < NKB) issue_loads(kb + 2);

        const uint32_t sbase = smem_base + (uint32_t)(kb % STAGES) * STAGE_BYTES;
        uint32_t QA[8], QB[8];
#pragma unroll
        for (int i = 0; i < 8; i++) { QA[i] = sbase + qa[i]; QB[i] = sbase + qb[i]; }

#pragma unroll
        for (int ks = 0; ks < 4; ks++) {
            const uint32_t c0 = (uint32_t)((2 * ks + 0) * 16);
            const uint32_t c1 = (uint32_t)((2 * ks + 1) * 16);
            float a[4][4];
#pragma unroll
            for (int mt = 0; mt < 4; mt++) {
                a[mt][0] = lds32(QA[mt * 2 + 0] ^ c0);
                a[mt][1] = lds32(QA[mt * 2 + 1] ^ c0);
                a[mt][2] = lds32(QA[mt * 2 + 0] ^ c1);
                a[mt][3] = lds32(QA[mt * 2 + 1] ^ c1);
            }
            float b[8][2];
#pragma unroll
            for (int nt = 0; nt < 8; nt++) {
                b[nt][0] = lds32(QB[nt] ^ c0);
                b[nt][1] = lds32(QB[nt] ^ c1);
            }
#pragma unroll
            for (int mt = 0; mt < 4; mt++)
#pragma unroll
                for (int nt = 0; nt < 8; nt++)
                    mma_tf32(acc[mt][nt], a[mt], b[nt]);
        }
    }

    // fused epilogue: out[tok, c] += w * (acc + bias[e, c])
#pragma unroll
    for (int mt = 0; mt < 4; mt++) {
        int r0 = warpM * 64 + mt * 16 + gid;
        int r1 = r0 + 8;
        int p0 = s_pid[r0];
        int p1 = s_pid[r1];
        float w0 = s_w[r0], w1 = s_w[r1];
        float* o0 = out + (size_t)s_tok[r0] * DDIM;
        float* o1 = out + (size_t)s_tok[r1] * DDIM;
#pragma unroll
        for (int nt = 0; nt < 8; nt++) {
            int c = n0 + warpN * 64 + nt * 8 + qid * 2;
            const float2 bv = *(const float2*)(eb + (size_t)e * DDIM + c);
            if (p0 >= 0) {
                red_add_f32(o0 + c + 0, w0 * (acc[mt][nt][0] + bv.x));
                red_add_f32(o0 + c + 1, w0 * (acc[mt][nt][1] + bv.y));
            }
            if (p1 >= 0) {
                red_add_f32(o1 + c + 0, w1 * (acc[mt][nt][2] + bv.x));
                red_add_f32(o1 + c + 1, w1 * (acc[mt][nt][3] + bv.y));
            }
        }
    }
}

// -------- launch --------
extern "C" void kernel_launch(void* const* d_in, const int* in_sizes, int n_in,
                              void* d_out, int out_size) {
    const float* input_feat = (const float*)d_in[0];
    const float* delta      = (const float*)d_in[1];
    const float* gate_W     = (const float*)d_in[2];
    const float* gate_b     = (const float*)d_in[3];
    const float* expert_W   = (const float*)d_in[4];
    const float* expert_b   = (const float*)d_in[5];
    float* out = (float*)d_out;

    cudaFuncSetAttribute(gemm_kernel, cudaFuncAttributeMaxDynamicSharedMemorySize, SMEM_BYTES);

    float* rdelta; cudaGetSymbolAddress((void**)&rdelta, g_rdelta);
    float* rW;     cudaGetSymbolAddress((void**)&rW, g_rW);

    cudaMemsetAsync(out, 0, (size_t)out_size * sizeof(float));
    round_kernel<<<(ND4 + NW4 + 255) / 256, 256>>>(delta, rdelta, expert_W, rW);
    gate_kernel<<<NTOK / 8, 256>>>(input_feat, gate_W, gate_b);
    group_kernel<<<NEXP, GT>>>();
    dim3 grid(DDIM / BN, NPAIR / BM, NEXP);
    gemm_kernel<<<grid, CTA_THREADS, SMEM_BYTES>>>(expert_b, out);
}

// round 15
// speedup vs baseline: 1.0876x; 1.0046x over previous
#include <cuda_runtime.h>
#include <cstdint>
#include <math.h>

// Problem constants
#define DDIM   1024
#define NEXP   8
#define NTOK   8192
#define NPAIR  (NTOK * 2)

// GEMM tiling: CTA 128x128 with 4 warps of 64x64, BK=32, 3-stage, 2 CTA/SM
#define BM 128
#define BN 128
#define BK 32
#define STAGES 3
#define CTA_THREADS 128
#define A_BYTES (BM * BK * 4)              // 16384
#define B_BYTES (BN * BK * 4)              // 16384
#define STAGE_BYTES (A_BYTES + B_BYTES)    // 32768
#define SMEM_BYTES (STAGES * STAGE_BYTES)  // 98304

// -------- device scratch --------
__device__ int   g_list[NEXP * NPAIR];
__device__ int   g_count[NEXP];
__device__ int   g_expert[NPAIR];
__device__ float g_weight[NPAIR];

// -------- helpers --------
__device__ __forceinline__ float to_tf32(float x) {
    uint32_t u;
    asm("cvt.rna.tf32.f32 %0, %1;" : "=r"(u) : "f"(x));
    return __uint_as_float(u);
}
__device__ __forceinline__ uint32_t smem_u32(const void* p) {
    uint32_t a;
    asm("{ .reg .u64 t; cvta.to.shared.u64 t, %1; cvt.u32.u64 %0, t; }" : "=r"(a) : "l"(p));
    return a;
}
__device__ __forceinline__ uint32_t swz128(uint32_t off) { return off ^ ((off >> 3) & 0x70u); }

__device__ __forceinline__ void cp_async16(uint32_t saddr, const void* gaddr) {
    asm volatile("cp.async.cg.shared.global [%0], [%1], 16;\n" :: "r"(saddr), "l"(gaddr));
}
__device__ __forceinline__ void cp_commit() { asm volatile("cp.async.commit_group;\n" ::: "memory"); }
template <int N>
__device__ __forceinline__ void cp_wait() { asm volatile("cp.async.wait_group %0;\n" :: "n"(N) : "memory"); }

// load + round to tf32 (rna) in one step — numerics identical to pre-rounding
__device__ __forceinline__ float lds32_tf32(uint32_t a) {
    float v;
    asm volatile("ld.shared.f32 %0, [%1];" : "=f"(v) : "r"(a));
    return to_tf32(v);
}
__device__ __forceinline__ void red_add_f32(float* gptr, float v) {
    asm volatile("red.global.add.f32 [%0], %1;" :: "l"(gptr), "f"(v) : "memory");
}

__device__ __forceinline__ void mma_tf32(float* c, const float* a, const float* b) {
    asm volatile(
        "mma.sync.aligned.m16n8k8.row.col.f32.tf32.tf32.f32 "
        "{%0,%1,%2,%3}, {%4,%5,%6,%7}, {%8,%9}, {%0,%1,%2,%3};\n"
        : "+f"(c[0]), "+f"(c[1]), "+f"(c[2]), "+f"(c[3])
        : "r"(__float_as_uint(a[0])), "r"(__float_as_uint(a[1])),
          "r"(__float_as_uint(a[2])), "r"(__float_as_uint(a[3])),
          "r"(__float_as_uint(b[0])), "r"(__float_as_uint(b[1])));
}

// -------- kernel 1: gating (one warp per token) --------
__global__ void gate_kernel(const float* __restrict__ x,
                            const float* __restrict__ gw,
                            const float* __restrict__ gb) {
    int warp = (blockIdx.x * blockDim.x + threadIdx.x) >> 5;
    int lane = threadIdx.x & 31;
    if (warp >= NTOK) return;
    const float* xr = x + (size_t)warp * DDIM;

    float acc[NEXP];
#pragma unroll
    for (int e = 0; e < NEXP; e++) acc[e] = 0.f;
    for (int i = lane; i < DDIM; i += 32) {
        float v = xr[i];
#pragma unroll
        for (int e = 0; e < NEXP; e++) acc[e] += v * gw[e * DDIM + i];
    }
#pragma unroll
    for (int e = 0; e < NEXP; e++) {
#pragma unroll
        for (int o = 16; o > 0; o >>= 1) acc[e] += __shfl_xor_sync(0xffffffffu, acc[e], o);
    }
    if (lane == 0) {
        float logits[NEXP];
#pragma unroll
        for (int e = 0; e < NEXP; e++) logits[e] = acc[e] + gb[e];
        int i0 = 0; float v0 = logits[0];
#pragma unroll
        for (int e = 1; e < NEXP; e++) if (logits[e] > v0) { v0 = logits[e]; i0 = e; }
        int i1 = -1; float v1 = -3.4e38f;
#pragma unroll
        for (int e = 0; e < NEXP; e++) if (e != i0 && logits[e] > v1) { v1 = logits[e]; i1 = e; }
        float e1 = expf(v1 - v0);
        float inv = 1.0f / (1.0f + e1);
        g_expert[warp * 2 + 0] = i0;
        g_expert[warp * 2 + 1] = i1;
        g_weight[warp * 2 + 0] = inv;
        g_weight[warp * 2 + 1] = e1 * inv;
    }
}

// -------- kernel 2: grouping, one block per expert --------
#define GT   1024
#define GPER (NPAIR / GT)   // 16
__global__ void __launch_bounds__(GT) group_kernel() {
    const int e = blockIdx.x;
    const int t = threadIdx.x;
    const int warp = t >> 5;
    const int lane = t & 31;
    __shared__ int s_tot[32];

    const int base = t * GPER;
    unsigned mask = 0;
    int cnt = 0;
#pragma unroll
    for (int i = 0; i < GPER; i++) {
        if (g_expert[base + i] == e) { mask |= (1u << i); cnt++; }
    }
    int incl = cnt;
#pragma unroll
    for (int o = 1; o < 32; o <<= 1) {
        int u = __shfl_up_sync(0xffffffffu, incl, o);
        if (lane >= o) incl += u;
    }
    if (lane == 31) s_tot[warp] = incl;
    __syncthreads();
    if (warp == 0) {
        int v = s_tot[lane];
        int orig = v;
#pragma unroll
        for (int o = 1; o < 32; o <<= 1) {
            int u = __shfl_up_sync(0xffffffffu, v, o);
            if (lane >= o) v += u;
        }
        if (lane == 31) g_count[e] = v;
        s_tot[lane] = v - orig;
    }
    __syncthreads();

    int off = s_tot[warp] + incl - cnt;
    int* lst = g_list + e * NPAIR;
    while (mask) {
        int i = __ffs(mask) - 1;
        mask &= mask - 1;
        lst[off++] = base + i;
    }
}

// -------- kernel 3: grouped GEMM, raw fp32 in smem, in-register tf32 cvt --------
__global__ void __launch_bounds__(CTA_THREADS, 2) gemm_kernel(const float* __restrict__ delta,
                                                              const float* __restrict__ W,
                                                              const float* __restrict__ eb,
                                                              float* __restrict__ out) {
    const int e   = blockIdx.z;
    const int cnt = g_count[e];
    const int m0  = blockIdx.y * BM;
    if (m0 >= cnt) return;
    const int n0  = blockIdx.x * BN;

    extern __shared__ __align__(1024) char smem[];
    __shared__ int   s_pid[BM];
    __shared__ int   s_tok[BM];
    __shared__ float s_w[BM];

    const uint32_t smem_base = smem_u32(smem);
    const int tid = threadIdx.x;
    const int wid = tid >> 5;
    const int lane = tid & 31;
    const int warpM = wid & 1;    // 2 x 64-row bands
    const int warpN = wid >> 1;   // 2 x 64-col bands
    const int gid = lane >> 2;    // 0..7
    const int qid = lane & 3;     // 0..3

    if (tid < BM) {
        int p = (m0 + tid < cnt) ? g_list[e * NPAIR + m0 + tid] : -1;
        s_pid[tid] = p;
        s_tok[tid] = (p >= 0) ? (p >> 1) : 0;
        s_w[tid]   = (p >= 0) ? g_weight[p] : 0.f;
    }
    __syncthreads();

    const float* __restrict__ Wb = W + (size_t)e * DDIM * DDIM;
    const int NKB = DDIM / BK;  // 32

    auto issue_loads = [&](int kb) {
        const uint32_t sbase = smem_base + (uint32_t)(kb % STAGES) * STAGE_BYTES;
        const int kbase = kb * BK;
#pragma unroll
        for (int i = 0; i < 8; i++) {
            int idx = tid + i * CTA_THREADS;
            int r = idx >> 3, c4 = idx & 7;
            const float* g = delta + (size_t)s_tok[r] * DDIM + kbase + c4 * 4;
            cp_async16(sbase + swz128((uint32_t)(r * 128 + c4 * 16)), g);
        }
#pragma unroll
        for (int i = 0; i < 8; i++) {
            int idx = tid + i * CTA_THREADS;
            int r = idx >> 3, c4 = idx & 7;
            const float* g = Wb + (size_t)(n0 + r) * DDIM + kbase + c4 * 4;
            cp_async16(sbase + A_BYTES + swz128((uint32_t)(r * 128 + c4 * 16)), g);
        }
        cp_commit();
    };

    // fragment addressing: Q = r*128 + qid*4 | ((r&7)<<4), r&7==gid
    uint32_t qa[8], qb[8];
#pragma unroll
    for (int mt = 0; mt < 4; mt++) {
        int r0 = warpM * 64 + mt * 16 + gid;
        int r1 = r0 + 8;
        qa[mt * 2 + 0] = (uint32_t)(r0 * 128 + qid * 4) | (uint32_t)((r0 & 7) << 4);
        qa[mt * 2 + 1] = (uint32_t)(r1 * 128 + qid * 4) | (uint32_t)((r1 & 7) << 4);
    }
#pragma unroll
    for (int nt = 0; nt < 8; nt++) {
        int n = warpN * 64 + nt * 8 + gid;
        qb[nt] = (uint32_t)(A_BYTES + n * 128 + qid * 4) | (uint32_t)((n & 7) << 4);
    }

    float acc[4][8][4];
#pragma unroll
    for (int mt = 0; mt < 4; mt++)
#pragma unroll
        for (int nt = 0; nt < 8; nt++)
#pragma unroll
            for (int j = 0; j < 4; j++) acc[mt][nt][j] = 0.f;

    issue_loads(0);
    issue_loads(1);

    for (int kb = 0; kb < NKB; kb++) {
        if (kb + 2 < NKB) cp_wait<1>(); else cp_wait<0>();
        __syncthreads();
        if (kb + 2 < NKB) issue_loads(kb + 2);

        const uint32_t sbase = smem_base + (uint32_t)(kb % STAGES) * STAGE_BYTES;
        uint32_t QA[8], QB[8];
#pragma unroll
        for (int i = 0; i < 8; i++) { QA[i] = sbase + qa[i]; QB[i] = sbase + qb[i]; }

#pragma unroll
        for (int ks = 0; ks < 4; ks++) {
            const uint32_t c0 = (uint32_t)((2 * ks + 0) * 16);
            const uint32_t c1 = (uint32_t)((2 * ks + 1) * 16);
            float a[4][4];
#pragma unroll
            for (int mt = 0; mt < 4; mt++) {
                a[mt][0] = lds32_tf32(QA[mt * 2 + 0] ^ c0);
                a[mt][1] = lds32_tf32(QA[mt * 2 + 1] ^ c0);
                a[mt][2] = lds32_tf32(QA[mt * 2 + 0] ^ c1);
                a[mt][3] = lds32_tf32(QA[mt * 2 + 1] ^ c1);
            }
            float b[8][2];
#pragma unroll
            for (int nt = 0; nt < 8; nt++) {
                b[nt][0] = lds32_tf32(QB[nt] ^ c0);
                b[nt][1] = lds32_tf32(QB[nt] ^ c1);
            }
#pragma unroll
            for (int mt = 0; mt < 4; mt++)
#pragma unroll
                for (int nt = 0; nt < 8; nt++)
                    mma_tf32(acc[mt][nt], a[mt], b[nt]);
        }
    }

    // fused epilogue: out[tok, c] += w * (acc + bias[e, c])
#pragma unroll
    for (int mt = 0; mt < 4; mt++) {
        int r0 = warpM * 64 + mt * 16 + gid;
        int r1 = r0 + 8;
        int p0 = s_pid[r0];
        int p1 = s_pid[r1];
        float w0 = s_w[r0], w1 = s_w[r1];
        float* o0 = out + (size_t)s_tok[r0] * DDIM;
        float* o1 = out + (size_t)s_tok[r1] * DDIM;
#pragma unroll
        for (int nt = 0; nt < 8; nt++) {
            int c = n0 + warpN * 64 + nt * 8 + qid * 2;
            const float2 bv = *(const float2*)(eb + (size_t)e * DDIM + c);
            if (p0 >= 0) {
                red_add_f32(o0 + c + 0, w0 * (acc[mt][nt][0] + bv.x));
                red_add_f32(o0 + c + 1, w0 * (acc[mt][nt][1] + bv.y));
            }
            if (p1 >= 0) {
                red_add_f32(o1 + c + 0, w1 * (acc[mt][nt][2] + bv.x));
                red_add_f32(o1 + c + 1, w1 * (acc[mt][nt][3] + bv.y));
            }
        }
    }
}

// -------- launch --------
extern "C" void kernel_launch(void* const* d_in, const int* in_sizes, int n_in,
                              void* d_out, int out_size) {
    const float* input_feat = (const float*)d_in[0];
    const float* delta      = (const float*)d_in[1];
    const float* gate_W     = (const float*)d_in[2];
    const float* gate_b     = (const float*)d_in[3];
    const float* expert_W   = (const float*)d_in[4];
    const float* expert_b   = (const float*)d_in[5];
    float* out = (float*)d_out;

    cudaFuncSetAttribute(gemm_kernel, cudaFuncAttributeMaxDynamicSharedMemorySize, SMEM_BYTES);

    cudaMemsetAsync(out, 0, (size_t)out_size * sizeof(float));
    gate_kernel<<<NTOK / 8, 256>>>(input_feat, gate_W, gate_b);
    group_kernel<<<NEXP, GT>>>();
    dim3 grid(DDIM / BN, NPAIR / BM, NEXP);
    gemm_kernel<<<grid, CTA_THREADS, SMEM_BYTES>>>(delta, expert_W, expert_b, out);
}